// round 2
// baseline (speedup 1.0000x reference)
#include <cuda_runtime.h>
#include <cstdint>

// ============================================================================
// ForexLSTM: 2-layer LSTM (B=512, T=1024, H=65) + final linear.
//
// Strategy:
//  - Batch rows are independent -> partition across CTAs, no cross-CTA sync.
//  - Per layer kernel: persistent T-loop. 128 CTAs x 4 rows, 288 threads.
//  - 260 "gate threads": each owns one gate g, holds W_ih[g][:], W_hh[g][:]
//    in REGISTERS as packed float2 (f32x2), accumulates with fma.rn.f32x2
//    (2 fp32 FMA lanes/inst -> full 128 FMA/cyc/SM rate).
//  - h/x tiles in smem, read as broadcast 128-bit shared loads (conflict-free).
//  - Same threads double as elementwise threads (r = tid/65, i = tid%65):
//    c update + tanh + h writeback, and x prefetch staging.
//  - x for t+1 prefetched into a register at step start -> DRAM latency hidden
//    behind ~1100-cycle gate compute.
// ============================================================================

using u32 = unsigned int;
using ull = unsigned long long;

constexpr int B = 512;
constexpr int T = 1024;
constexpr int H = 65;
constexpr int G4 = 260;      // 4*H gates
constexpr int RPC = 4;       // rows per CTA
constexpr int NCTA = 128;    // 128 * 4 = 512 rows
constexpr int NTHR = 288;    // 9 warps; threads [0,260) do the work
constexpr int ROWP = 68;     // padded row stride in floats (16B aligned, pads=0)

__device__ float g_buf1[(size_t)B * T * H];  // layer0 output sequence
__device__ float g_buf2[(size_t)B * T * H];  // layer1 output (only t=T-1 written)

// ---------------- packed f32x2 helpers ----------------
__device__ __forceinline__ ull pack2(float x, float y) {
    ull r;
    asm("mov.b64 %0, {%1, %2};" : "=l"(r) : "f"(x), "f"(y));
    return r;
}
__device__ __forceinline__ float2 unpack2(ull v) {
    float2 r;
    asm("mov.b64 {%0, %1}, %2;" : "=f"(r.x), "=f"(r.y) : "l"(v));
    return r;
}
__device__ __forceinline__ void fma2(ull& d, ull a, ull b) {
    asm("fma.rn.f32x2 %0, %1, %2, %0;" : "+l"(d) : "l"(a), "l"(b));
}
__device__ __forceinline__ void lds128(ull& a, ull& b, u32 addr) {
    asm volatile("ld.shared.v2.u64 {%0, %1}, [%2];" : "=l"(a), "=l"(b) : "r"(addr));
}
__device__ __forceinline__ ull lds64(u32 addr) {
    ull a;
    asm volatile("ld.shared.u64 %0, [%1];" : "=l"(a) : "r"(addr));
    return a;
}

// sigmoid(v) = 1/(1+e^-v)    (inf-safe: e^inf -> inf -> rcp -> 0)
// tanh(v)    = 1 - 2/(e^{2v}+1)  (inf-safe both directions)
__device__ __forceinline__ float fast_sigmoid(float v) {
    return __fdividef(1.0f, 1.0f + __expf(-v));
}
__device__ __forceinline__ float fast_tanh(float v) {
    return 1.0f - 2.0f * __fdividef(1.0f, __expf(2.0f * v) + 1.0f);
}

// ============================================================================
// LSTM layer kernel. layer==0: x_ext -> g_buf1 (write all t)
//                    layer==1: g_buf1 -> g_buf2 (write only t=T-1)
// ============================================================================
__global__ void __launch_bounds__(NTHR, 1)
lstm_layer_kernel(const float* __restrict__ x_ext,
                  const float* __restrict__ w_ih,
                  const float* __restrict__ w_hh,
                  const float* __restrict__ b_ih,
                  const float* __restrict__ b_hh,
                  int layer)
{
    const float* x_in = (layer == 0) ? x_ext : g_buf1;
    float* h_out      = (layer == 0) ? g_buf1 : g_buf2;
    const bool write_all = (layer == 0);

    __shared__ __align__(16) float h_sm[RPC * ROWP];
    __shared__ __align__(16) float x_sm[2][RPC * ROWP];
    __shared__ float gates_sm[RPC * G4];

    const int tid = threadIdx.x;
    const int b0  = blockIdx.x * RPC;
    const bool active = (tid < G4);

    // ---- per-thread weight registers (gate g = tid) ----
    ull wih[33], whh[33];
    float bg = 0.0f;
    const int g = tid;
    if (active) {
        const float* wi = w_ih + g * H;
        const float* wh = w_hh + g * H;
#pragma unroll
        for (int j = 0; j < 32; j++) {
            wih[j] = pack2(__ldg(wi + 2 * j), __ldg(wi + 2 * j + 1));
            whh[j] = pack2(__ldg(wh + 2 * j), __ldg(wh + 2 * j + 1));
        }
        wih[32] = pack2(__ldg(wi + 64), 0.0f);
        whh[32] = pack2(__ldg(wh + 64), 0.0f);
        bg = __ldg(b_ih + g) + __ldg(b_hh + g);
    }

    // ---- elementwise mapping (same threads) ----
    const int r_e = active ? (tid / H) : 0;
    const int i_e = active ? (tid % H) : 0;
    const float* xptr = x_in + ((size_t)(b0 + r_e) * T) * H + i_e;
    float* optr       = h_out + ((size_t)(b0 + r_e) * T) * H + i_e;

    // ---- init smem (zeros; pads stay zero forever) ----
    for (int k = tid; k < RPC * ROWP; k += NTHR) h_sm[k] = 0.0f;
    for (int k = tid; k < 2 * RPC * ROWP; k += NTHR) (&x_sm[0][0])[k] = 0.0f;
    __syncthreads();
    if (active) x_sm[0][r_e * ROWP + i_e] = xptr[0];
    __syncthreads();

    float c = 0.0f;

    const u32 h_base  = (u32)__cvta_generic_to_shared(h_sm);
    const u32 x_base0 = (u32)__cvta_generic_to_shared(&x_sm[0][0]);
    const u32 x_base1 = x_base0 + RPC * ROWP * 4;

    const bool is_t = (g >= 130 && g < 195);  // tanh gate range

    for (int t = 0; t < T; t++) {
        const int cur = t & 1;

        // prefetch x for t+1 (register; stored to smem in elementwise phase)
        float xn = 0.0f;
        if (active) {
            int tn = (t + 1 < T) ? (t + 1) : (T - 1);
            xn = __ldg(xptr + (size_t)tn * H);
        }

        // ---- gate compute: gates[r][g] = bg + x.Wih^T + h.Whh^T ----
        if (active) {
            const u32 xb = cur ? x_base1 : x_base0;
#pragma unroll
            for (int r = 0; r < RPC; r++) {
                ull aH = 0ull, aX = 0ull;  // (0.0f, 0.0f)
                const u32 ha = h_base + r * (ROWP * 4);
                const u32 xa = xb     + r * (ROWP * 4);
#pragma unroll
                for (int q = 0; q < 16; q++) {
                    ull h0, h1, x0, x1;
                    lds128(h0, h1, ha + q * 16);
                    lds128(x0, x1, xa + q * 16);
                    fma2(aH, whh[2 * q],     h0);
                    fma2(aH, whh[2 * q + 1], h1);
                    fma2(aX, wih[2 * q],     x0);
                    fma2(aX, wih[2 * q + 1], x1);
                }
                // tail i=64 (pair with zero pad at i=65)
                fma2(aH, whh[32], lds64(ha + 256));
                fma2(aX, wih[32], lds64(xa + 256));

                float2 sH = unpack2(aH);
                float2 sX = unpack2(aX);
                float v = ((sH.x + sH.y) + (sX.x + sX.y)) + bg;

                // i/f/o -> sigmoid, g -> tanh (branch-free via predication)
                float z = is_t ? 2.0f * v : v;
                float s = __fdividef(1.0f, 1.0f + __expf(-z));
                float a = is_t ? (2.0f * s - 1.0f) : s;
                gates_sm[r * G4 + g] = a;
            }
        }
        __syncthreads();

        // ---- elementwise: c,h update; stage prefetched x ----
        if (active) {
            const float* gr = gates_sm + r_e * G4;
            float iv = gr[i_e];
            float fv = gr[65 + i_e];
            float gv = gr[130 + i_e];
            float ov = gr[195 + i_e];
            c = fv * c + iv * gv;
            float hv = ov * fast_tanh(c);
            h_sm[r_e * ROWP + i_e] = hv;
            x_sm[cur ^ 1][r_e * ROWP + i_e] = xn;
            if (write_all || t == T - 1) optr[(size_t)t * H] = hv;
        }
        __syncthreads();
    }
}

// ============================================================================
// Final linear: out[b] = h2[b, T-1, :] . w_lin + b_lin
// ============================================================================
__global__ void final_linear_kernel(const float* __restrict__ w_lin,
                                    const float* __restrict__ b_lin,
                                    float* __restrict__ out)
{
    __shared__ float w[72];
    const int tid = threadIdx.x;
    if (tid < H) w[tid] = w_lin[tid];
    __syncthreads();
    const int b = blockIdx.x * blockDim.x + tid;
    if (b < B) {
        const float* h = g_buf2 + ((size_t)b * T + (T - 1)) * H;
        float s = b_lin[0];
#pragma unroll
        for (int i = 0; i < H; i++) s += h[i] * w[i];
        out[b] = s;
    }
}

// ============================================================================
extern "C" void kernel_launch(void* const* d_in, const int* in_sizes, int n_in,
                              void* d_out, int out_size)
{
    const float* x     = (const float*)d_in[0];
    const float* w_ih0 = (const float*)d_in[1];
    const float* w_hh0 = (const float*)d_in[2];
    const float* b_ih0 = (const float*)d_in[3];
    const float* b_hh0 = (const float*)d_in[4];
    const float* w_ih1 = (const float*)d_in[5];
    const float* w_hh1 = (const float*)d_in[6];
    const float* b_ih1 = (const float*)d_in[7];
    const float* b_hh1 = (const float*)d_in[8];
    const float* w_lin = (const float*)d_in[9];
    const float* b_lin = (const float*)d_in[10];

    lstm_layer_kernel<<<NCTA, NTHR>>>(x, w_ih0, w_hh0, b_ih0, b_hh0, 0);
    lstm_layer_kernel<<<NCTA, NTHR>>>(nullptr, w_ih1, w_hh1, b_ih1, b_hh1, 1);
    final_linear_kernel<<<2, 256>>>(w_lin, b_lin, (float*)d_out);
}

// round 3
// speedup vs baseline: 1.0493x; 1.0493x over previous
#include <cuda_runtime.h>
#include <cstdint>

// ============================================================================
// ForexLSTM: 2-layer LSTM (B=512, T=1024, H=65) + final linear.
//
// R2 restructure:
//  - pre_kernel: pre[b,t,g] = bias[g] + x[b,t,:]·W_ih[g,:]  — fully parallel
//    GEMM, 2 CTAs/SM, register-resident weights, packed fma.rn.f32x2.
//  - recur_kernel: per step only gates = pre[t] + h·W_hh^T. 544 threads:
//    520 gate threads (gate g × 2 rows each), 17 warps/SM, short FMA chains.
//    pre[t+1] prefetched via coalesced LDG a full step ahead.
//  - final_linear on last-step h of layer 1.
// ============================================================================

using u32 = unsigned int;
using ull = unsigned long long;

constexpr int B = 512, T = 1024, H = 65, G4 = 260;
constexpr int GROUPS = (B * T) / 4;   // 131072 groups of 4 rows
constexpr int PTHR = 288, PGRID = 296;
constexpr int RTHR = 544, RGRID = 128, RPC = 4;

__device__ float g_pre[(size_t)B * T * G4];   // 545 MB scratch (static, legal)
__device__ float g_h1 [(size_t)B * T * H];    // layer-0 full output sequence
__device__ float g_hN [B * H];                // layer-1 last-step h

// ---------------- packed f32x2 helpers ----------------
__device__ __forceinline__ ull pack2(float x, float y) {
    ull r; asm("mov.b64 %0, {%1, %2};" : "=l"(r) : "f"(x), "f"(y)); return r;
}
__device__ __forceinline__ float2 unpack2(ull v) {
    float2 r; asm("mov.b64 {%0, %1}, %2;" : "=f"(r.x), "=f"(r.y) : "l"(v)); return r;
}
__device__ __forceinline__ void fma2(ull& d, ull a, ull b) {
    asm("fma.rn.f32x2 %0, %1, %2, %0;" : "+l"(d) : "l"(a), "l"(b));
}
__device__ __forceinline__ void lds128(ull& a, ull& b, u32 addr) {
    asm volatile("ld.shared.v2.u64 {%0, %1}, [%2];" : "=l"(a), "=l"(b) : "r"(addr));
}
__device__ __forceinline__ ull lds64(u32 addr) {
    ull a; asm volatile("ld.shared.u64 %0, [%1];" : "=l"(a) : "r"(addr)); return a;
}
__device__ __forceinline__ float fast_tanh(float v) {
    // inf-safe both directions
    return 1.0f - 2.0f * __fdividef(1.0f, __expf(2.0f * v) + 1.0f);
}

// ============================================================================
// pre[row, g] = (b_ih[g]+b_hh[g]) + sum_i xin[row, i] * w_ih[g, i]
// row = b*T + t, xin is [B*T, 65] contiguous (x or g_h1).
// Each iteration: 4 rows staged in padded smem (row stride 68 floats, pads=0),
// each of 260 threads computes its gate for all 4 rows (register weights).
// ============================================================================
__global__ void __launch_bounds__(PTHR, 2)
pre_kernel(const float* __restrict__ x_ext,
           const float* __restrict__ w_ih,
           const float* __restrict__ b_ih,
           const float* __restrict__ b_hh,
           int layer)
{
    const float* xin = (layer == 0) ? x_ext : g_h1;

    __shared__ __align__(16) float xs[2][4 * 68];
    const int tid = threadIdx.x;
    const bool act = tid < G4;

    ull wih[33]; float bg = 0.f;
    if (act) {
        const float* wi = w_ih + tid * H;
#pragma unroll
        for (int j = 0; j < 32; j++)
            wih[j] = pack2(__ldg(wi + 2 * j), __ldg(wi + 2 * j + 1));
        wih[32] = pack2(__ldg(wi + 64), 0.f);
        bg = __ldg(b_ih + tid) + __ldg(b_hh + tid);
    }
    for (int k = tid; k < 2 * 272; k += PTHR) (&xs[0][0])[k] = 0.f;
    __syncthreads();

    const int sidx = act ? ((tid / 65) * 68 + tid % 65) : 0;
    int gi = blockIdx.x;
    if (act) xs[0][sidx] = __ldg(xin + (size_t)gi * 260 + tid);
    __syncthreads();

    const u32 xb = (u32)__cvta_generic_to_shared(&xs[0][0]);
    int cur = 0;
    for (; gi < GROUPS; gi += PGRID) {
        const int gn = gi + PGRID;
        float xn = 0.f;
        if (act && gn < GROUPS) xn = __ldg(xin + (size_t)gn * 260 + tid);

        if (act) {
            ull a0 = pack2(bg, 0.f), a1 = a0, a2 = a0, a3 = a0;
            const u32 bA = xb + cur * (272 * 4);
#pragma unroll
            for (int q = 0; q < 16; q++) {
                ull u0, u1;
                lds128(u0, u1, bA + 0 * 272 + q * 16);
                fma2(a0, wih[2 * q], u0); fma2(a0, wih[2 * q + 1], u1);
                lds128(u0, u1, bA + 1 * 272 + q * 16);
                fma2(a1, wih[2 * q], u0); fma2(a1, wih[2 * q + 1], u1);
                lds128(u0, u1, bA + 2 * 272 + q * 16);
                fma2(a2, wih[2 * q], u0); fma2(a2, wih[2 * q + 1], u1);
                lds128(u0, u1, bA + 3 * 272 + q * 16);
                fma2(a3, wih[2 * q], u0); fma2(a3, wih[2 * q + 1], u1);
            }
            fma2(a0, wih[32], lds64(bA + 0 * 272 + 256));
            fma2(a1, wih[32], lds64(bA + 1 * 272 + 256));
            fma2(a2, wih[32], lds64(bA + 2 * 272 + 256));
            fma2(a3, wih[32], lds64(bA + 3 * 272 + 256));

            float* op = g_pre + ((size_t)gi * 4) * G4 + tid;
            float2 s;
            s = unpack2(a0); op[0]       = s.x + s.y;
            s = unpack2(a1); op[G4]      = s.x + s.y;
            s = unpack2(a2); op[2 * G4]  = s.x + s.y;
            s = unpack2(a3); op[3 * G4]  = s.x + s.y;
        }
        if (act && gn < GROUPS) xs[cur ^ 1][sidx] = xn;
        __syncthreads();
        cur ^= 1;
    }
}

// ============================================================================
// Recurrent kernel: gates = pre[t] + h·W_hh^T, then LSTM cell update.
// 128 CTAs × 4 rows. 544 threads: tid<520 gate threads (g=tid%260, row pair
// rh=tid/260); tid<260 double as elementwise threads (r=tid/65, i=tid%65).
// ============================================================================
__global__ void __launch_bounds__(RTHR, 1)
recur_kernel(const float* __restrict__ w_hh, int write_all)
{
    float* hout = write_all ? g_h1 : g_hN;

    __shared__ __align__(16) float h_sm[4 * 68];
    __shared__ float gates_sm[4 * G4];

    const int tid = threadIdx.x;
    const int b0  = blockIdx.x * RPC;
    const bool gact = tid < 520;
    const int g  = tid % G4;
    const int rh = tid / G4;   // 0/1 for gate threads -> rows 2rh, 2rh+1

    ull whh[33];
    if (gact) {
        const float* wh = w_hh + g * H;
#pragma unroll
        for (int j = 0; j < 32; j++)
            whh[j] = pack2(__ldg(wh + 2 * j), __ldg(wh + 2 * j + 1));
        whh[32] = pack2(__ldg(wh + 64), 0.f);
    }

    const bool eact = tid < G4;
    const int r_e = tid / H, i_e = tid % H;

    // pre pointers for this thread's two rows (guarded by gact at deref)
    const int rr = (rh < 2) ? rh : 0;
    const float* p0 = g_pre + ((size_t)(b0 + 2 * rr)     * T) * G4 + g;
    const float* p1 = g_pre + ((size_t)(b0 + 2 * rr + 1) * T) * G4 + g;
    const int re  = (r_e < 4) ? r_e : 0;
    float* op = write_all ? hout + ((size_t)(b0 + re) * T) * H + i_e
                          : hout + (size_t)(b0 + re) * H + i_e;

    for (int k = tid; k < 272; k += RTHR) h_sm[k] = 0.f;
    __syncthreads();

    const u32 hb = (u32)__cvta_generic_to_shared(h_sm);
    const bool is_t = (g >= 130 && g < 195);
    float c = 0.f;
    float pv0 = 0.f, pv1 = 0.f;
    if (gact) { pv0 = __ldg(p0); pv1 = __ldg(p1); }

    for (int t = 0; t < T; t++) {
        // prefetch pre for t+1 (consumed next step; ~full step of latency)
        float pn0 = 0.f, pn1 = 0.f;
        if (gact && t + 1 < T) {
            pn0 = __ldg(p0 + (size_t)(t + 1) * G4);
            pn1 = __ldg(p1 + (size_t)(t + 1) * G4);
        }

        if (gact) {
            ull a0 = 0ull, a1 = 0ull;
            const u32 hA = hb + (2 * rh) * 272;
            const u32 hB = hA + 272;
#pragma unroll
            for (int q = 0; q < 16; q++) {
                ull u0, u1, v0, v1;
                lds128(u0, u1, hA + q * 16);
                lds128(v0, v1, hB + q * 16);
                fma2(a0, whh[2 * q], u0); fma2(a0, whh[2 * q + 1], u1);
                fma2(a1, whh[2 * q], v0); fma2(a1, whh[2 * q + 1], v1);
            }
            fma2(a0, whh[32], lds64(hA + 256));
            fma2(a1, whh[32], lds64(hB + 256));

            float2 s0 = unpack2(a0), s1 = unpack2(a1);
            float v0 = (s0.x + s0.y) + pv0;
            float v1 = (s1.x + s1.y) + pv1;
            // i/f/o -> sigmoid ; g -> tanh = 2*sigmoid(2v)-1 (branch-free)
            float z0 = is_t ? 2.f * v0 : v0;
            float z1 = is_t ? 2.f * v1 : v1;
            float sg0 = __fdividef(1.f, 1.f + __expf(-z0));
            float sg1 = __fdividef(1.f, 1.f + __expf(-z1));
            gates_sm[(2 * rh) * G4 + g]     = is_t ? (2.f * sg0 - 1.f) : sg0;
            gates_sm[(2 * rh + 1) * G4 + g] = is_t ? (2.f * sg1 - 1.f) : sg1;
        }
        __syncthreads();

        if (eact) {
            const float* gr = gates_sm + r_e * G4;
            float iv = gr[i_e];
            float fv = gr[65 + i_e];
            float gv = gr[130 + i_e];
            float ov = gr[195 + i_e];
            c = fv * c + iv * gv;
            float hv = ov * fast_tanh(c);
            h_sm[r_e * 68 + i_e] = hv;
            if (write_all)        op[(size_t)t * H] = hv;
            else if (t == T - 1)  op[0] = hv;
        }
        pv0 = pn0; pv1 = pn1;
        __syncthreads();
    }
}

// ============================================================================
// out[b] = g_hN[b,:] . w_lin + b_lin
// ============================================================================
__global__ void final_linear_kernel(const float* __restrict__ w_lin,
                                    const float* __restrict__ b_lin,
                                    float* __restrict__ out)
{
    __shared__ float w[72];
    const int tid = threadIdx.x;
    if (tid < H) w[tid] = __ldg(w_lin + tid);
    __syncthreads();
    const int b = blockIdx.x * blockDim.x + tid;
    if (b < B) {
        const float* h = g_hN + (size_t)b * H;
        float s = __ldg(b_lin);
#pragma unroll
        for (int i = 0; i < H; i++) s += h[i] * w[i];
        out[b] = s;
    }
}

// ============================================================================
extern "C" void kernel_launch(void* const* d_in, const int* in_sizes, int n_in,
                              void* d_out, int out_size)
{
    const float* x     = (const float*)d_in[0];
    const float* w_ih0 = (const float*)d_in[1];
    const float* w_hh0 = (const float*)d_in[2];
    const float* b_ih0 = (const float*)d_in[3];
    const float* b_hh0 = (const float*)d_in[4];
    const float* w_ih1 = (const float*)d_in[5];
    const float* w_hh1 = (const float*)d_in[6];
    const float* b_ih1 = (const float*)d_in[7];
    const float* b_hh1 = (const float*)d_in[8];
    const float* w_lin = (const float*)d_in[9];
    const float* b_lin = (const float*)d_in[10];

    pre_kernel<<<PGRID, PTHR>>>(x, w_ih0, b_ih0, b_hh0, 0);
    recur_kernel<<<RGRID, RTHR>>>(w_hh0, 1);
    pre_kernel<<<PGRID, PTHR>>>(x, w_ih1, b_ih1, b_hh1, 1);
    recur_kernel<<<RGRID, RTHR>>>(w_hh1, 0);
    final_linear_kernel<<<2, 256>>>(w_lin, b_lin, (float*)d_out);
}